// round 11
// baseline (speedup 1.0000x reference)
#include <cuda_runtime.h>
#include <cstdint>

namespace {

constexpr int NT = 512;  // threads per CTA (16 warps)

struct Smem {
  float F [64][64];
  float S [64][64];       // side state: H (side0) or T (side1)
  float U [64][64];       // xcat staging, then F + LN-out
  float W [64][64];       // w1 or w2
  float TR[64][64];       // transform (dead after P1)
  float WEb[2][64][64];   // ping-pong: cor[j] * S[j][:]
  float SAV[2][64][64];   // sparse row snapshots (pre-overwrite)
  unsigned m0[64], m1[64];    // adjacency bitmasks
  float degf[64];
  float gmm[64], bet[64], bias[64];
  unsigned fr0[4], fr1[4];    // frontier words per hop 0..3
  int   cnt[3];
  unsigned char tasks[3][64];
};

__device__ __forceinline__ float rsum16(float v, unsigned m) {
  v += __shfl_xor_sync(m, v, 8);
  v += __shfl_xor_sync(m, v, 4);
  v += __shfl_xor_sync(m, v, 2);
  v += __shfl_xor_sync(m, v, 1);
  return v;
}
__device__ __forceinline__ void fma4(float4& a, float s, const float4& b) {
  a.x = fmaf(s, b.x, a.x); a.y = fmaf(s, b.y, a.y);
  a.z = fmaf(s, b.z, a.z); a.w = fmaf(s, b.w, a.w);
}
__device__ __forceinline__ void add4(float4& a, const float4& b) {
  a.x += b.x; a.y += b.y; a.z += b.z; a.w += b.w;
}
__device__ __forceinline__ float4 sum4(const float4& a, const float4& b) {
  return make_float4(a.x + b.x, a.y + b.y, a.z + b.z, a.w + b.w);
}
__device__ __forceinline__ void relu4(float4& a) {
  a.x = fmaxf(a.x, 0.f); a.y = fmaxf(a.y, 0.f);
  a.z = fmaxf(a.z, 0.f); a.w = fmaxf(a.w, 0.f);
}
__device__ __forceinline__ bool bitr(unsigned w0, unsigned w1, int r) {
  return ((r < 32 ? (w0 >> r) : (w1 >> (r - 32))) & 1u) != 0u;
}
__device__ __forceinline__ uint32_t smem_u32(const void* p) {
  uint32_t a;
  asm("{ .reg .u64 t; cvta.to.shared.u64 t, %1; cvt.u32.u64 %0, t; }" : "=r"(a) : "l"(p));
  return a;
}
__device__ __forceinline__ uint32_t mapa_u32(uint32_t addr, uint32_t rank) {
  uint32_t r;
  asm("mapa.shared::cluster.u32 %0, %1, %2;" : "=r"(r) : "r"(addr), "r"(rank));
  return r;
}
__device__ __forceinline__ float4 ld_ds4(uint32_t addr) {
  uint32_t a, b, c, d;
  asm volatile("ld.shared::cluster.v4.b32 {%0,%1,%2,%3}, [%4];"
               : "=r"(a), "=r"(b), "=r"(c), "=r"(d) : "r"(addr));
  float4 v;
  v.x = __uint_as_float(a); v.y = __uint_as_float(b);
  v.z = __uint_as_float(c); v.w = __uint_as_float(d);
  return v;
}
#define CLUSTER_SYNC_() do { \
  asm volatile("barrier.cluster.arrive.aligned;" ::: "memory"); \
  asm volatile("barrier.cluster.wait.aligned;"   ::: "memory"); \
} while (0)

__global__ __launch_bounds__(NT, 1) __cluster_dims__(2, 1, 1)
void lagat_kernel(const float* __restrict__ adj,
                  const float* __restrict__ feat_node,
                  const int*   __restrict__ idx,
                  const int*   __restrict__ head_ids,
                  const int*   __restrict__ tail_ids,
                  const float* __restrict__ transform,
                  const float* __restrict__ embed,
                  const float* __restrict__ w1, const float* __restrict__ b1,
                  const float* __restrict__ w2, const float* __restrict__ b2,
                  const float* __restrict__ gamma1, const float* __restrict__ beta1,
                  const float* __restrict__ gamma2, const float* __restrict__ beta2,
                  float* __restrict__ out)
{
  extern __shared__ float smem_raw[];
  Smem& s = *reinterpret_cast<Smem*>(smem_raw);
  const int g    = blockIdx.x >> 1;
  const int side = blockIdx.x & 1;      // 0 = head chain, 1 = tail chain
  const int tid  = threadIdx.x;
  const int w    = tid >> 5;
  const int l    = tid & 31;
  const int li   = l & 15;
  const int h16  = l >> 4;
  const int hw   = w * 2 + h16;         // half-warp id 0..31
  const unsigned hm = (l < 16) ? 0x0000FFFFu : 0xFFFF0000u;
  const int base = g * 64;

  // ---- earliest: the only 2-deep dependent LDG chain (idx -> embed) --------
  const int xrow = tid >> 3, xcol = tid & 7;
  const int id = idx[base + xrow];                       // LDG #1 of chain
  const int hl = head_ids[g] - base;
  const int tl = tail_ids[g] - base;

  float4* F4  = reinterpret_cast<float4*>(&s.F [0][0]);
  float4* S4  = reinterpret_cast<float4*>(&s.S [0][0]);
  float4* U4  = reinterpret_cast<float4*>(&s.U [0][0]);
  float4* W4  = reinterpret_cast<float4*>(&s.W [0][0]);
  float4* TR4 = reinterpret_cast<float4*>(&s.TR[0][0]);
  float4* WEa = reinterpret_cast<float4*>(&s.WEb[0][0][0]);
  float4* WEbp= reinterpret_cast<float4*>(&s.WEb[1][0][0]);
  float4* SV4 = reinterpret_cast<float4*>(&s.SAV[0][0][0]);
  const float4* gm4 = reinterpret_cast<const float4*>(s.gmm);
  const float4* bt4 = reinterpret_cast<const float4*>(s.bet);
  const float4* bi4 = reinterpret_cast<const float4*>(s.bias);

  const uint32_t sbase   = smem_u32(&s);
  const uint32_t off_S   = (uint32_t)((const char*)&s.S[0][0]      - (const char*)&s);
  const uint32_t off_SAV = (uint32_t)((const char*)&s.SAV[0][0][0] - (const char*)&s);
  const uint32_t pbase   = mapa_u32(sbase, (uint32_t)(side ^ 1));

  const int c_own = side ? tl : hl;   // BFS center for this chain
  const int c_qry = side ? hl : tl;   // query center (opposite)

  const float* Wsrc = side ? w2 : w1;
  const float* Gsrc = side ? gamma2 : gamma1;
  const float* Bsrc = side ? beta2  : beta1;
  const float* bsrc = side ? b2 : b1;

  // ---------------- P0: loads + adjacency bitmask ---------------------------
  const float4 xg = *reinterpret_cast<const float4*>(embed + (size_t)id * 32 + xcol * 4);
  const float4 xf = *reinterpret_cast<const float4*>(feat_node + (base + xrow) * 32 + xcol * 4);
  {
    float av[4][2];
    #pragma unroll
    for (int rr = 0; rr < 4; ++rr) {
      const float* arow = adj + (size_t)(base + w * 4 + rr) * 4096 + base;
      av[rr][0] = arow[l];
      av[rr][1] = arow[l + 32];
    }
    #pragma unroll
    for (int rr = 0; rr < 4; ++rr) {
      const unsigned b0 = __ballot_sync(0xFFFFFFFFu, av[rr][0] != 0.f);
      const unsigned b1 = __ballot_sync(0xFFFFFFFFu, av[rr][1] != 0.f);
      if (l == 0) {
        const int r = w * 4 + rr;
        s.m0[r] = b0; s.m1[r] = b1;
        s.degf[r] = (float)(__popc(b0) + __popc(b1));
      }
    }
  }
  #pragma unroll
  for (int e = tid; e < 1024; e += NT) {
    TR4[e] = reinterpret_cast<const float4*>(transform)[e];
    W4[e]  = reinterpret_cast<const float4*>(Wsrc)[e];
  }
  U4[xrow * 16 + xcol]     = xf;
  U4[xrow * 16 + 8 + xcol] = xg;
  if (tid < 64) {
    s.gmm[tid] = Gsrc[tid]; s.bet[tid] = Bsrc[tid]; s.bias[tid] = bsrc[tid];
  }
  __syncthreads();

  // ---------------- P1: ALL 64 F rows, 2 rows per half-warp (W shared) ------
  {
    const int ra = hw;          // rows hw and hw+32
    const int rb = hw + 32;
    float4 aa = make_float4(0.f, 0.f, 0.f, 0.f);
    float4 ab = make_float4(0.f, 0.f, 0.f, 0.f);
    #pragma unroll
    for (int kb = 0; kb < 16; ++kb) {
      const float4 xa = U4[ra * 16 + kb];
      const float4 xb = U4[rb * 16 + kb];
      float4 wq;
      wq = TR4[(4 * kb + 0) * 16 + li]; fma4(aa, xa.x, wq); fma4(ab, xb.x, wq);
      wq = TR4[(4 * kb + 1) * 16 + li]; fma4(aa, xa.y, wq); fma4(ab, xb.y, wq);
      wq = TR4[(4 * kb + 2) * 16 + li]; fma4(aa, xa.z, wq); fma4(ab, xb.z, wq);
      wq = TR4[(4 * kb + 3) * 16 + li]; fma4(aa, xa.w, wq); fma4(ab, xb.w, wq);
    }
    F4[ra * 16 + li] = aa; S4[ra * 16 + li] = aa;
    F4[rb * 16 + li] = ab; S4[rb * 16 + li] = ab;
    if (side == 0) {
      *reinterpret_cast<float4*>(out + (size_t)(base + ra) * 256 + li * 4) = aa;
      *reinterpret_cast<float4*>(out + (size_t)(base + rb) * 256 + li * 4) = ab;
    }
  }

  // ---------------- frontier masks (hops 0..3) + task lists (warp 0) --------
  if (w == 0) {
    const unsigned c0bit = (c_own < 32) ? 1u << c_own : 0u;
    const unsigned c1bit = (c_own >= 32) ? 1u << (c_own - 32) : 0u;
    const unsigned f1_0 = s.m0[c_own] | c0bit;
    const unsigned f1_1 = s.m1[c_own] | c1bit;
    const bool a2 = bitr(f1_0, f1_1, l)      || (s.m0[l] & f1_0)      || (s.m1[l] & f1_1);
    const bool b2 = bitr(f1_0, f1_1, l + 32) || (s.m0[l + 32] & f1_0) || (s.m1[l + 32] & f1_1);
    const unsigned f2_0 = __ballot_sync(0xFFFFFFFFu, a2);
    const unsigned f2_1 = __ballot_sync(0xFFFFFFFFu, b2);
    const bool a3 = bitr(f2_0, f2_1, l)      || (s.m0[l] & f2_0)      || (s.m1[l] & f2_1);
    const bool b3 = bitr(f2_0, f2_1, l + 32) || (s.m0[l + 32] & f2_0) || (s.m1[l + 32] & f2_1);
    const unsigned f3_0 = __ballot_sync(0xFFFFFFFFu, a3);
    const unsigned f3_1 = __ballot_sync(0xFFFFFFFFu, b3);
    unsigned fw0[4] = { c0bit, f1_0, f2_0, f3_0 };
    unsigned fw1[4] = { c1bit, f1_1, f2_1, f3_1 };
    const unsigned below = (1u << l) - 1u;
    #pragma unroll
    for (int hp = 0; hp < 4; ++hp) {
      if (l == 0) { s.fr0[hp] = fw0[hp]; s.fr1[hp] = fw1[hp]; }
      if (hp < 3) {
        if ((fw0[hp] >> l) & 1u) s.tasks[hp][__popc(fw0[hp] & below)] = (unsigned char)l;
        if ((fw1[hp] >> l) & 1u) s.tasks[hp][__popc(fw0[hp]) + __popc(fw1[hp] & below)] = (unsigned char)(l + 32);
        if (l == 0) s.cnt[hp] = __popc(fw0[hp]) + __popc(fw1[hp]);
      }
    }
  }
  __syncthreads();

  // query row of F is constant across all iterations
  const float4 q = F4[c_qry * 16 + li];

  // ---------------- WE init (buffer 0) for fr[3] rows, from F ---------------
  {
    const unsigned nb0 = s.fr0[3], nb1 = s.fr1[3];
    #pragma unroll
    for (int p = 0; p < 2; ++p) {
      const int r = w * 4 + p * 2 + h16;
      if (bitr(nb0, nb1, r)) {
        const float4 sv = F4[r * 16 + li];
        float c = rsum16(sv.x * q.x + sv.y * q.y + sv.z * q.z + sv.w * q.w, hm);
        c = fabsf(c);
        WEa[r * 16 + li] = make_float4(c * sv.x, c * sv.y, c * sv.z, c * sv.w);
      }
    }
  }
  __syncthreads();

  // ---------------- main loop: it = 0,1,2 (hop = 2,1,0) ---------------------
  for (int it = 0; it < 3; ++it) {
    const int hop = 2 - it;
    const int cnt = s.cnt[hop];
    float4* WEc = (it & 1) ? WEbp : WEa;   // read buffer
    float4* WEn = (it & 1) ? WEa  : WEbp;  // write buffer (next iter's read)

    if (cnt > 32) {
      // ---- paired path: fused B+C, 2 tasks per half-warp, shared W reads ---
      for (int t2 = hw; 2 * t2 < cnt; t2 += 32) {
        const int ia = 2 * t2;
        const int ib = ia + 1;
        const int ra = s.tasks[hop][ia];
        const int rb = (ib < cnt) ? (int)s.tasks[hop][ib] : -1;

        #pragma unroll
        for (int qq = 0; qq < 2; ++qq) {
          const int r = qq ? rb : ra;
          if (r < 0) continue;
          unsigned mm0 = s.m0[r], mm1 = s.m1[r];
          float4 a0 = make_float4(0.f, 0.f, 0.f, 0.f);
          float4 a1 = make_float4(0.f, 0.f, 0.f, 0.f);
          while (mm0) { const int j = __ffs(mm0) - 1;  mm0 &= mm0 - 1; add4(a0, WEc[j * 16 + li]); }
          while (mm1) { const int j = __ffs(mm1) + 31; mm1 &= mm1 - 1; add4(a1, WEc[j * 16 + li]); }
          add4(a0, a1);
          a0.x = (a0.x >= 0.f) ? a0.x : 0.01f * a0.x;
          a0.y = (a0.y >= 0.f) ? a0.y : 0.01f * a0.y;
          a0.z = (a0.z >= 0.f) ? a0.z : 0.01f * a0.z;
          a0.w = (a0.w >= 0.f) ? a0.w : 0.01f * a0.w;
          const float inv = 1.f / (s.degf[r] + 1e-8f);
          a0.x *= inv; a0.y *= inv; a0.z *= inv; a0.w *= inv;
          // one-pass LN: two independent reduction chains (interleaved)
          float s1 = a0.x + a0.y + a0.z + a0.w;
          float s2 = a0.x * a0.x + a0.y * a0.y + a0.z * a0.z + a0.w * a0.w;
          s1 = rsum16(s1, hm);
          s2 = rsum16(s2, hm);
          const float mu  = s1 * (1.f / 64.f);
          const float var = fmaxf(s2 * (1.f / 64.f) - mu * mu, 0.f);
          const float rs  = rsqrtf(var + 1e-5f);
          const float4 d = make_float4(a0.x - mu, a0.y - mu, a0.z - mu, a0.w - mu);
          const float4 gg = gm4[li];
          const float4 bb = bt4[li];
          const float4 fv = F4[r * 16 + li];
          float4 u;
          u.x = fv.x + fmaf(gg.x * rs, d.x, bb.x);
          u.y = fv.y + fmaf(gg.y * rs, d.y, bb.y);
          u.z = fv.z + fmaf(gg.z * rs, d.z, bb.z);
          u.w = fv.w + fmaf(gg.w * rs, d.w, bb.w);
          U4[r * 16 + li] = u;
        }
        __syncwarp(hm);

        float4 aa = bi4[li];
        float4 ab = aa;
        if (rb >= 0) {
          #pragma unroll
          for (int kb = 0; kb < 16; ++kb) {
            const float4 xa = U4[ra * 16 + kb];
            const float4 xb = U4[rb * 16 + kb];
            float4 wq;
            wq = W4[(4 * kb + 0) * 16 + li]; fma4(aa, xa.x, wq); fma4(ab, xb.x, wq);
            wq = W4[(4 * kb + 1) * 16 + li]; fma4(aa, xa.y, wq); fma4(ab, xb.y, wq);
            wq = W4[(4 * kb + 2) * 16 + li]; fma4(aa, xa.z, wq); fma4(ab, xb.z, wq);
            wq = W4[(4 * kb + 3) * 16 + li]; fma4(aa, xa.w, wq); fma4(ab, xb.w, wq);
          }
        } else {
          #pragma unroll
          for (int kb = 0; kb < 16; ++kb) {
            const float4 xv = U4[ra * 16 + kb];
            fma4(aa, xv.x, W4[(4 * kb + 0) * 16 + li]);
            fma4(aa, xv.y, W4[(4 * kb + 1) * 16 + li]);
            fma4(aa, xv.z, W4[(4 * kb + 2) * 16 + li]);
            fma4(aa, xv.w, W4[(4 * kb + 3) * 16 + li]);
          }
        }
        relu4(aa);
        if (it) SV4[(it - 1) * 1024 + ra * 16 + li] = S4[ra * 16 + li];
        S4[ra * 16 + li] = aa;
        if (it < 2) {
          float c = rsum16(aa.x * q.x + aa.y * q.y + aa.z * q.z + aa.w * q.w, hm);
          c = fabsf(c);
          WEn[ra * 16 + li] = make_float4(c * aa.x, c * aa.y, c * aa.z, c * aa.w);
        }
        if (rb >= 0) {
          relu4(ab);
          if (it) SV4[(it - 1) * 1024 + rb * 16 + li] = S4[rb * 16 + li];
          S4[rb * 16 + li] = ab;
          if (it < 2) {
            float c = rsum16(ab.x * q.x + ab.y * q.y + ab.z * q.z + ab.w * q.w, hm);
            c = fabsf(c);
            WEn[rb * 16 + li] = make_float4(c * ab.x, c * ab.y, c * ab.z, c * ab.w);
          }
        }
      }
    } else {
      // ---- serial path: one WARP per task, K-split GEMM across half-warps --
      for (int t = w; t < cnt; t += 16) {
        const int r = s.tasks[hop][t];
        // B + LN: both halves compute identical results (no divergence)
        unsigned mm0 = s.m0[r], mm1 = s.m1[r];
        float4 a0 = make_float4(0.f, 0.f, 0.f, 0.f);
        float4 a1 = make_float4(0.f, 0.f, 0.f, 0.f);
        while (mm0) { const int j = __ffs(mm0) - 1;  mm0 &= mm0 - 1; add4(a0, WEc[j * 16 + li]); }
        while (mm1) { const int j = __ffs(mm1) + 31; mm1 &= mm1 - 1; add4(a1, WEc[j * 16 + li]); }
        add4(a0, a1);
        a0.x = (a0.x >= 0.f) ? a0.x : 0.01f * a0.x;
        a0.y = (a0.y >= 0.f) ? a0.y : 0.01f * a0.y;
        a0.z = (a0.z >= 0.f) ? a0.z : 0.01f * a0.z;
        a0.w = (a0.w >= 0.f) ? a0.w : 0.01f * a0.w;
        const float inv = 1.f / (s.degf[r] + 1e-8f);
        a0.x *= inv; a0.y *= inv; a0.z *= inv; a0.w *= inv;
        float s1 = a0.x + a0.y + a0.z + a0.w;
        float s2 = a0.x * a0.x + a0.y * a0.y + a0.z * a0.z + a0.w * a0.w;
        s1 = rsum16(s1, hm);
        s2 = rsum16(s2, hm);
        const float mu  = s1 * (1.f / 64.f);
        const float var = fmaxf(s2 * (1.f / 64.f) - mu * mu, 0.f);
        const float rs  = rsqrtf(var + 1e-5f);
        const float4 d = make_float4(a0.x - mu, a0.y - mu, a0.z - mu, a0.w - mu);
        const float4 gg = gm4[li];
        const float4 bb = bt4[li];
        const float4 fv = F4[r * 16 + li];
        float4 u;
        u.x = fv.x + fmaf(gg.x * rs, d.x, bb.x);
        u.y = fv.y + fmaf(gg.y * rs, d.y, bb.y);
        u.z = fv.z + fmaf(gg.z * rs, d.z, bb.z);
        u.w = fv.w + fmaf(gg.w * rs, d.w, bb.w);
        if (h16 == 0) U4[r * 16 + li] = u;
        __syncwarp();

        // C GEMM: half h16 covers kb in [8*h16, 8*h16+8)
        float4 acc = (h16 == 0) ? bi4[li] : make_float4(0.f, 0.f, 0.f, 0.f);
        const int kb0 = h16 * 8;
        #pragma unroll
        for (int kk = 0; kk < 8; ++kk) {
          const int kb = kb0 + kk;
          const float4 xv = U4[r * 16 + kb];
          fma4(acc, xv.x, W4[(4 * kb + 0) * 16 + li]);
          fma4(acc, xv.y, W4[(4 * kb + 1) * 16 + li]);
          fma4(acc, xv.z, W4[(4 * kb + 2) * 16 + li]);
          fma4(acc, xv.w, W4[(4 * kb + 3) * 16 + li]);
        }
        // combine the two half partials (both halves end with the total)
        acc.x += __shfl_xor_sync(0xFFFFFFFFu, acc.x, 16);
        acc.y += __shfl_xor_sync(0xFFFFFFFFu, acc.y, 16);
        acc.z += __shfl_xor_sync(0xFFFFFFFFu, acc.z, 16);
        acc.w += __shfl_xor_sync(0xFFFFFFFFu, acc.w, 16);
        relu4(acc);
        if (h16 == 0) {
          if (it) SV4[(it - 1) * 1024 + r * 16 + li] = S4[r * 16 + li];
          S4[r * 16 + li] = acc;
        }
        if (it < 2) {
          float c = rsum16(acc.x * q.x + acc.y * q.y + acc.z * q.z + acc.w * q.w, hm);
          c = fabsf(c);
          if (h16 == 0)
            WEn[r * 16 + li] = make_float4(c * acc.x, c * acc.y, c * acc.z, c * acc.w);
        }
      }
    }
    if (it < 2) __syncthreads();
    // after it=2 the cluster barrier below provides the block-wide sync
  }

  // ---------------- tail: per-row layer reconstruction + DSMEM add ----------
  CLUSTER_SYNC_();
  {
    const int r  = side * 32 + (tid >> 4), c4 = tid & 15;  // own half rows
    const int i4 = r * 16 + c4;
    // own-side selects
    const bool o1 = bitr(s.fr0[1], s.fr1[1], r);   // overwritten at it=1
    const bool o0 = (r == c_own);                  // overwritten at it=2
    // peer-side masks (computable locally: same adjacency, peer center = c_qry)
    const unsigned p10 = s.m0[c_qry] | (c_qry < 32 ? 1u << c_qry : 0u);
    const unsigned p11 = s.m1[c_qry] | (c_qry >= 32 ? 1u << (c_qry - 32) : 0u);
    const bool pp1 = bitr(p10, p11, r);
    const bool pp0 = (r == c_qry);

    const float4 oS = S4[i4];
    const float4 pS = ld_ds4(pbase + off_S + (uint32_t)i4 * 16u);
    const float4 o2 = o0 ? SV4[1024 + i4] : oS;
    const float4 p2 = pp0 ? ld_ds4(pbase + off_SAV + (uint32_t)(1024 + i4) * 16u) : pS;
    const float4 o1v = o1 ? SV4[i4] : o2;
    const float4 p1v = pp1 ? ld_ds4(pbase + off_SAV + (uint32_t)i4 * 16u) : p2;

    float* ob = out + (size_t)(base + r) * 256 + c4 * 4;
    *reinterpret_cast<float4*>(ob +  64) = sum4(o1v, p1v);
    *reinterpret_cast<float4*>(ob + 128) = sum4(o2,  p2);
    *reinterpret_cast<float4*>(ob + 192) = sum4(oS,  pS);
  }
  CLUSTER_SYNC_();   // peer may still be reading our smem
}

} // namespace

extern "C" void kernel_launch(void* const* d_in, const int* in_sizes, int n_in,
                              void* d_out, int out_size) {
  const float* adj       = (const float*)d_in[0];
  const float* feat_node = (const float*)d_in[1];
  const int*   idx       = (const int*)  d_in[2];
  const int*   head_ids  = (const int*)  d_in[3];
  const int*   tail_ids  = (const int*)  d_in[4];
  // d_in[5] = graph_indices (implicit in block layout)
  const float* transform = (const float*)d_in[6];
  const float* embed     = (const float*)d_in[7];
  const float* w1        = (const float*)d_in[8];
  const float* b1        = (const float*)d_in[9];
  const float* w2        = (const float*)d_in[10];
  const float* b2        = (const float*)d_in[11];
  const float* gamma1    = (const float*)d_in[12];
  const float* beta1     = (const float*)d_in[13];
  const float* gamma2    = (const float*)d_in[14];
  const float* beta2     = (const float*)d_in[15];
  float* out = (float*)d_out;

  const int smem = (int)sizeof(Smem);
  cudaFuncSetAttribute(lagat_kernel, cudaFuncAttributeMaxDynamicSharedMemorySize, smem);
  lagat_kernel<<<128, NT, smem>>>(adj, feat_node, idx, head_ids, tail_ids,
                                  transform, embed, w1, b1, w2, b2,
                                  gamma1, beta1, gamma2, beta2, out);
}

// round 12
// speedup vs baseline: 1.0099x; 1.0099x over previous
#include <cuda_runtime.h>
#include <cstdint>

namespace {

constexpr int NT = 512;  // threads per CTA (16 warps)

struct Smem {
  float F [64][64];
  float S [64][64];       // side state: H (side0) or T (side1)
  float U [64][64];       // xcat staging, then F + LN-out
  float W [64][64];       // w1 or w2
  float TR[64][64];       // transform (dead after P1)
  float WEb[2][64][64];   // ping-pong: cor[j] * S[j][:]
  float SAV[2][64][64];   // sparse row snapshots (pre-overwrite)
  unsigned m0[64], m1[64];    // adjacency bitmasks
  float degf[64];
  float gmm[64], bet[64], bias[64];
  unsigned fr0[4], fr1[4];    // frontier words per hop 0..3
  int   cnt[3];
  unsigned char tasks[3][64];
};

__device__ __forceinline__ float rsum16(float v, unsigned m) {
  v += __shfl_xor_sync(m, v, 8);
  v += __shfl_xor_sync(m, v, 4);
  v += __shfl_xor_sync(m, v, 2);
  v += __shfl_xor_sync(m, v, 1);
  return v;
}
__device__ __forceinline__ void fma4(float4& a, float s, const float4& b) {
  a.x = fmaf(s, b.x, a.x); a.y = fmaf(s, b.y, a.y);
  a.z = fmaf(s, b.z, a.z); a.w = fmaf(s, b.w, a.w);
}
__device__ __forceinline__ void add4(float4& a, const float4& b) {
  a.x += b.x; a.y += b.y; a.z += b.z; a.w += b.w;
}
__device__ __forceinline__ float4 sum4(const float4& a, const float4& b) {
  return make_float4(a.x + b.x, a.y + b.y, a.z + b.z, a.w + b.w);
}
__device__ __forceinline__ void relu4(float4& a) {
  a.x = fmaxf(a.x, 0.f); a.y = fmaxf(a.y, 0.f);
  a.z = fmaxf(a.z, 0.f); a.w = fmaxf(a.w, 0.f);
}
__device__ __forceinline__ bool bitr(unsigned w0, unsigned w1, int r) {
  return ((r < 32 ? (w0 >> r) : (w1 >> (r - 32))) & 1u) != 0u;
}
__device__ __forceinline__ uint32_t smem_u32(const void* p) {
  uint32_t a;
  asm("{ .reg .u64 t; cvta.to.shared.u64 t, %1; cvt.u32.u64 %0, t; }" : "=r"(a) : "l"(p));
  return a;
}
__device__ __forceinline__ uint32_t mapa_u32(uint32_t addr, uint32_t rank) {
  uint32_t r;
  asm("mapa.shared::cluster.u32 %0, %1, %2;" : "=r"(r) : "r"(addr), "r"(rank));
  return r;
}
__device__ __forceinline__ float4 ld_ds4(uint32_t addr) {
  uint32_t a, b, c, d;
  asm volatile("ld.shared::cluster.v4.b32 {%0,%1,%2,%3}, [%4];"
               : "=r"(a), "=r"(b), "=r"(c), "=r"(d) : "r"(addr));
  float4 v;
  v.x = __uint_as_float(a); v.y = __uint_as_float(b);
  v.z = __uint_as_float(c); v.w = __uint_as_float(d);
  return v;
}
#define CLUSTER_SYNC_() do { \
  asm volatile("barrier.cluster.arrive.aligned;" ::: "memory"); \
  asm volatile("barrier.cluster.wait.aligned;"   ::: "memory"); \
} while (0)

__global__ __launch_bounds__(NT, 1) __cluster_dims__(2, 1, 1)
void lagat_kernel(const float* __restrict__ adj,
                  const float* __restrict__ feat_node,
                  const int*   __restrict__ idx,
                  const int*   __restrict__ head_ids,
                  const int*   __restrict__ tail_ids,
                  const float* __restrict__ transform,
                  const float* __restrict__ embed,
                  const float* __restrict__ w1, const float* __restrict__ b1,
                  const float* __restrict__ w2, const float* __restrict__ b2,
                  const float* __restrict__ gamma1, const float* __restrict__ beta1,
                  const float* __restrict__ gamma2, const float* __restrict__ beta2,
                  float* __restrict__ out)
{
  extern __shared__ float smem_raw[];
  Smem& s = *reinterpret_cast<Smem*>(smem_raw);
  const int g    = blockIdx.x >> 1;
  const int side = blockIdx.x & 1;      // 0 = head chain, 1 = tail chain
  const int tid  = threadIdx.x;
  const int w    = tid >> 5;
  const int l    = tid & 31;
  const int li   = l & 15;
  const int h16  = l >> 4;
  const int hw   = w * 2 + h16;         // half-warp id 0..31
  const unsigned hm = (l < 16) ? 0x0000FFFFu : 0xFFFF0000u;
  const int base = g * 64;

  // ---- earliest: the only 2-deep dependent LDG chain (idx -> embed) --------
  const int xrow = tid >> 3, xcol = tid & 7;
  const int id = idx[base + xrow];                       // LDG #1 of chain
  const int hl = head_ids[g] - base;
  const int tl = tail_ids[g] - base;

  float4* F4  = reinterpret_cast<float4*>(&s.F [0][0]);
  float4* S4  = reinterpret_cast<float4*>(&s.S [0][0]);
  float4* U4  = reinterpret_cast<float4*>(&s.U [0][0]);
  float4* W4  = reinterpret_cast<float4*>(&s.W [0][0]);
  float4* TR4 = reinterpret_cast<float4*>(&s.TR[0][0]);
  float4* WEa = reinterpret_cast<float4*>(&s.WEb[0][0][0]);
  float4* WEbp= reinterpret_cast<float4*>(&s.WEb[1][0][0]);
  float4* SV4 = reinterpret_cast<float4*>(&s.SAV[0][0][0]);
  const float4* gm4 = reinterpret_cast<const float4*>(s.gmm);
  const float4* bt4 = reinterpret_cast<const float4*>(s.bet);
  const float4* bi4 = reinterpret_cast<const float4*>(s.bias);

  const uint32_t sbase   = smem_u32(&s);
  const uint32_t off_S   = (uint32_t)((const char*)&s.S[0][0]      - (const char*)&s);
  const uint32_t off_SAV = (uint32_t)((const char*)&s.SAV[0][0][0] - (const char*)&s);
  const uint32_t pbase   = mapa_u32(sbase, (uint32_t)(side ^ 1));

  const int c_own = side ? tl : hl;   // BFS center for this chain
  const int c_qry = side ? hl : tl;   // query center (opposite)

  const float* Wsrc = side ? w2 : w1;
  const float* Gsrc = side ? gamma2 : gamma1;
  const float* Bsrc = side ? beta2  : beta1;
  const float* bsrc = side ? b2 : b1;

  // ---------------- P0: loads + adjacency bitmask ---------------------------
  const float4 xg = *reinterpret_cast<const float4*>(embed + (size_t)id * 32 + xcol * 4);
  const float4 xf = *reinterpret_cast<const float4*>(feat_node + (base + xrow) * 32 + xcol * 4);
  {
    float av[4][2];
    #pragma unroll
    for (int rr = 0; rr < 4; ++rr) {
      const float* arow = adj + (size_t)(base + w * 4 + rr) * 4096 + base;
      av[rr][0] = arow[l];
      av[rr][1] = arow[l + 32];
    }
    #pragma unroll
    for (int rr = 0; rr < 4; ++rr) {
      const unsigned b0 = __ballot_sync(0xFFFFFFFFu, av[rr][0] != 0.f);
      const unsigned b1 = __ballot_sync(0xFFFFFFFFu, av[rr][1] != 0.f);
      if (l == 0) {
        const int r = w * 4 + rr;
        s.m0[r] = b0; s.m1[r] = b1;
        s.degf[r] = (float)(__popc(b0) + __popc(b1));
      }
    }
  }
  #pragma unroll
  for (int e = tid; e < 1024; e += NT) {
    TR4[e] = reinterpret_cast<const float4*>(transform)[e];
    W4[e]  = reinterpret_cast<const float4*>(Wsrc)[e];
  }
  U4[xrow * 16 + xcol]     = xf;
  U4[xrow * 16 + 8 + xcol] = xg;
  if (tid < 64) {
    s.gmm[tid] = Gsrc[tid]; s.bet[tid] = Bsrc[tid]; s.bias[tid] = bsrc[tid];
  }
  __syncthreads();

  // ---------------- P1: ALL 64 F rows, 2 rows per half-warp (W shared) ------
  {
    const int ra = hw;          // rows hw and hw+32
    const int rb = hw + 32;
    float4 aa = make_float4(0.f, 0.f, 0.f, 0.f);
    float4 ab = make_float4(0.f, 0.f, 0.f, 0.f);
    #pragma unroll
    for (int kb = 0; kb < 16; ++kb) {
      const float4 xa = U4[ra * 16 + kb];
      const float4 xb = U4[rb * 16 + kb];
      float4 wq;
      wq = TR4[(4 * kb + 0) * 16 + li]; fma4(aa, xa.x, wq); fma4(ab, xb.x, wq);
      wq = TR4[(4 * kb + 1) * 16 + li]; fma4(aa, xa.y, wq); fma4(ab, xb.y, wq);
      wq = TR4[(4 * kb + 2) * 16 + li]; fma4(aa, xa.z, wq); fma4(ab, xb.z, wq);
      wq = TR4[(4 * kb + 3) * 16 + li]; fma4(aa, xa.w, wq); fma4(ab, xb.w, wq);
    }
    F4[ra * 16 + li] = aa; S4[ra * 16 + li] = aa;
    F4[rb * 16 + li] = ab; S4[rb * 16 + li] = ab;
    if (side == 0) {
      *reinterpret_cast<float4*>(out + (size_t)(base + ra) * 256 + li * 4) = aa;
      *reinterpret_cast<float4*>(out + (size_t)(base + rb) * 256 + li * 4) = ab;
    }
  }

  // ---------------- frontier masks (hops 0..3) + task lists (warp 0) --------
  if (w == 0) {
    const unsigned c0bit = (c_own < 32) ? 1u << c_own : 0u;
    const unsigned c1bit = (c_own >= 32) ? 1u << (c_own - 32) : 0u;
    const unsigned f1_0 = s.m0[c_own] | c0bit;
    const unsigned f1_1 = s.m1[c_own] | c1bit;
    const bool a2 = bitr(f1_0, f1_1, l)      || (s.m0[l] & f1_0)      || (s.m1[l] & f1_1);
    const bool b2 = bitr(f1_0, f1_1, l + 32) || (s.m0[l + 32] & f1_0) || (s.m1[l + 32] & f1_1);
    const unsigned f2_0 = __ballot_sync(0xFFFFFFFFu, a2);
    const unsigned f2_1 = __ballot_sync(0xFFFFFFFFu, b2);
    const bool a3 = bitr(f2_0, f2_1, l)      || (s.m0[l] & f2_0)      || (s.m1[l] & f2_1);
    const bool b3 = bitr(f2_0, f2_1, l + 32) || (s.m0[l + 32] & f2_0) || (s.m1[l + 32] & f2_1);
    const unsigned f3_0 = __ballot_sync(0xFFFFFFFFu, a3);
    const unsigned f3_1 = __ballot_sync(0xFFFFFFFFu, b3);
    unsigned fw0[4] = { c0bit, f1_0, f2_0, f3_0 };
    unsigned fw1[4] = { c1bit, f1_1, f2_1, f3_1 };
    const unsigned below = (1u << l) - 1u;
    #pragma unroll
    for (int hp = 0; hp < 4; ++hp) {
      if (l == 0) { s.fr0[hp] = fw0[hp]; s.fr1[hp] = fw1[hp]; }
      if (hp < 3) {
        if ((fw0[hp] >> l) & 1u) s.tasks[hp][__popc(fw0[hp] & below)] = (unsigned char)l;
        if ((fw1[hp] >> l) & 1u) s.tasks[hp][__popc(fw0[hp]) + __popc(fw1[hp] & below)] = (unsigned char)(l + 32);
        if (l == 0) s.cnt[hp] = __popc(fw0[hp]) + __popc(fw1[hp]);
      }
    }
  }
  __syncthreads();

  // query row of F is constant across all iterations
  const float4 q = F4[c_qry * 16 + li];

  // ---------------- WE init (buffer 0) for fr[3] rows, from F ---------------
  {
    const unsigned nb0 = s.fr0[3], nb1 = s.fr1[3];
    #pragma unroll
    for (int p = 0; p < 2; ++p) {
      const int r = w * 4 + p * 2 + h16;
      if (bitr(nb0, nb1, r)) {
        const float4 sv = F4[r * 16 + li];
        float c = rsum16(sv.x * q.x + sv.y * q.y + sv.z * q.z + sv.w * q.w, hm);
        c = fabsf(c);
        WEa[r * 16 + li] = make_float4(c * sv.x, c * sv.y, c * sv.z, c * sv.w);
      }
    }
  }
  __syncthreads();

  // ---------------- main loop: it = 0,1,2 (hop = 2,1,0) ---------------------
  for (int it = 0; it < 3; ++it) {
    const int hop = 2 - it;
    const int cnt = s.cnt[hop];
    float4* WEc = (it & 1) ? WEbp : WEa;   // read buffer
    float4* WEn = (it & 1) ? WEa  : WEbp;  // write buffer (next iter's read)

    if (cnt > 32) {
      // ---- paired path: fused B+C, 2 tasks per half-warp, shared W reads ---
      for (int t2 = hw; 2 * t2 < cnt; t2 += 32) {
        const int ia = 2 * t2;
        const int ib = ia + 1;
        const int ra = s.tasks[hop][ia];
        const int rb = (ib < cnt) ? (int)s.tasks[hop][ib] : -1;

        #pragma unroll
        for (int qq = 0; qq < 2; ++qq) {
          const int r = qq ? rb : ra;
          if (r < 0) continue;
          unsigned mm0 = s.m0[r], mm1 = s.m1[r];
          float4 a0 = make_float4(0.f, 0.f, 0.f, 0.f);
          float4 a1 = make_float4(0.f, 0.f, 0.f, 0.f);
          while (mm0) { const int j = __ffs(mm0) - 1;  mm0 &= mm0 - 1; add4(a0, WEc[j * 16 + li]); }
          while (mm1) { const int j = __ffs(mm1) + 31; mm1 &= mm1 - 1; add4(a1, WEc[j * 16 + li]); }
          add4(a0, a1);
          a0.x = (a0.x >= 0.f) ? a0.x : 0.01f * a0.x;
          a0.y = (a0.y >= 0.f) ? a0.y : 0.01f * a0.y;
          a0.z = (a0.z >= 0.f) ? a0.z : 0.01f * a0.z;
          a0.w = (a0.w >= 0.f) ? a0.w : 0.01f * a0.w;
          const float inv = 1.f / (s.degf[r] + 1e-8f);
          a0.x *= inv; a0.y *= inv; a0.z *= inv; a0.w *= inv;
          // one-pass LN: two independent reduction chains (interleaved)
          float s1 = a0.x + a0.y + a0.z + a0.w;
          float s2 = a0.x * a0.x + a0.y * a0.y + a0.z * a0.z + a0.w * a0.w;
          s1 = rsum16(s1, hm);
          s2 = rsum16(s2, hm);
          const float mu  = s1 * (1.f / 64.f);
          const float var = fmaxf(s2 * (1.f / 64.f) - mu * mu, 0.f);
          const float rs  = rsqrtf(var + 1e-5f);
          const float4 d = make_float4(a0.x - mu, a0.y - mu, a0.z - mu, a0.w - mu);
          const float4 gg = gm4[li];
          const float4 bb = bt4[li];
          const float4 fv = F4[r * 16 + li];
          float4 u;
          u.x = fv.x + fmaf(gg.x * rs, d.x, bb.x);
          u.y = fv.y + fmaf(gg.y * rs, d.y, bb.y);
          u.z = fv.z + fmaf(gg.z * rs, d.z, bb.z);
          u.w = fv.w + fmaf(gg.w * rs, d.w, bb.w);
          U4[r * 16 + li] = u;
        }
        __syncwarp(hm);

        float4 aa = bi4[li];
        float4 ab = aa;
        if (rb >= 0) {
          #pragma unroll
          for (int kb = 0; kb < 16; ++kb) {
            const float4 xa = U4[ra * 16 + kb];
            const float4 xb = U4[rb * 16 + kb];
            float4 wq;
            wq = W4[(4 * kb + 0) * 16 + li]; fma4(aa, xa.x, wq); fma4(ab, xb.x, wq);
            wq = W4[(4 * kb + 1) * 16 + li]; fma4(aa, xa.y, wq); fma4(ab, xb.y, wq);
            wq = W4[(4 * kb + 2) * 16 + li]; fma4(aa, xa.z, wq); fma4(ab, xb.z, wq);
            wq = W4[(4 * kb + 3) * 16 + li]; fma4(aa, xa.w, wq); fma4(ab, xb.w, wq);
          }
        } else {
          #pragma unroll
          for (int kb = 0; kb < 16; ++kb) {
            const float4 xv = U4[ra * 16 + kb];
            fma4(aa, xv.x, W4[(4 * kb + 0) * 16 + li]);
            fma4(aa, xv.y, W4[(4 * kb + 1) * 16 + li]);
            fma4(aa, xv.z, W4[(4 * kb + 2) * 16 + li]);
            fma4(aa, xv.w, W4[(4 * kb + 3) * 16 + li]);
          }
        }
        relu4(aa);
        if (it) SV4[(it - 1) * 1024 + ra * 16 + li] = S4[ra * 16 + li];
        S4[ra * 16 + li] = aa;
        if (it < 2) {
          float c = rsum16(aa.x * q.x + aa.y * q.y + aa.z * q.z + aa.w * q.w, hm);
          c = fabsf(c);
          WEn[ra * 16 + li] = make_float4(c * aa.x, c * aa.y, c * aa.z, c * aa.w);
        }
        if (rb >= 0) {
          relu4(ab);
          if (it) SV4[(it - 1) * 1024 + rb * 16 + li] = S4[rb * 16 + li];
          S4[rb * 16 + li] = ab;
          if (it < 2) {
            float c = rsum16(ab.x * q.x + ab.y * q.y + ab.z * q.z + ab.w * q.w, hm);
            c = fabsf(c);
            WEn[rb * 16 + li] = make_float4(c * ab.x, c * ab.y, c * ab.z, c * ab.w);
          }
        }
      }
    } else {
      // ---- serial path (R9 form): one task per half-warp, fused B+LN+GEMM --
      for (int t = hw; t < cnt; t += 32) {
        const int r = s.tasks[hop][t];
        unsigned mm0 = s.m0[r], mm1 = s.m1[r];
        float4 a0 = make_float4(0.f, 0.f, 0.f, 0.f);
        float4 a1 = make_float4(0.f, 0.f, 0.f, 0.f);
        while (mm0) { const int j = __ffs(mm0) - 1;  mm0 &= mm0 - 1; add4(a0, WEc[j * 16 + li]); }
        while (mm1) { const int j = __ffs(mm1) + 31; mm1 &= mm1 - 1; add4(a1, WEc[j * 16 + li]); }
        add4(a0, a1);
        a0.x = (a0.x >= 0.f) ? a0.x : 0.01f * a0.x;
        a0.y = (a0.y >= 0.f) ? a0.y : 0.01f * a0.y;
        a0.z = (a0.z >= 0.f) ? a0.z : 0.01f * a0.z;
        a0.w = (a0.w >= 0.f) ? a0.w : 0.01f * a0.w;
        const float inv = 1.f / (s.degf[r] + 1e-8f);
        a0.x *= inv; a0.y *= inv; a0.z *= inv; a0.w *= inv;
        float s1 = a0.x + a0.y + a0.z + a0.w;
        float s2 = a0.x * a0.x + a0.y * a0.y + a0.z * a0.z + a0.w * a0.w;
        s1 = rsum16(s1, hm);
        s2 = rsum16(s2, hm);
        const float mu  = s1 * (1.f / 64.f);
        const float var = fmaxf(s2 * (1.f / 64.f) - mu * mu, 0.f);
        const float rs  = rsqrtf(var + 1e-5f);
        const float4 d = make_float4(a0.x - mu, a0.y - mu, a0.z - mu, a0.w - mu);
        const float4 gg = gm4[li];
        const float4 bb = bt4[li];
        const float4 fv = F4[r * 16 + li];
        float4 u;
        u.x = fv.x + fmaf(gg.x * rs, d.x, bb.x);
        u.y = fv.y + fmaf(gg.y * rs, d.y, bb.y);
        u.z = fv.z + fmaf(gg.z * rs, d.z, bb.z);
        u.w = fv.w + fmaf(gg.w * rs, d.w, bb.w);
        U4[r * 16 + li] = u;
        __syncwarp(hm);

        float4 acc = bi4[li];
        #pragma unroll
        for (int kb = 0; kb < 16; ++kb) {
          const float4 xv = U4[r * 16 + kb];
          fma4(acc, xv.x, W4[(4 * kb + 0) * 16 + li]);
          fma4(acc, xv.y, W4[(4 * kb + 1) * 16 + li]);
          fma4(acc, xv.z, W4[(4 * kb + 2) * 16 + li]);
          fma4(acc, xv.w, W4[(4 * kb + 3) * 16 + li]);
        }
        relu4(acc);
        if (it) SV4[(it - 1) * 1024 + r * 16 + li] = S4[r * 16 + li];
        S4[r * 16 + li] = acc;
        if (it < 2) {
          float c = rsum16(acc.x * q.x + acc.y * q.y + acc.z * q.z + acc.w * q.w, hm);
          c = fabsf(c);
          WEn[r * 16 + li] = make_float4(c * acc.x, c * acc.y, c * acc.z, c * acc.w);
        }
      }
    }
    if (it < 2) __syncthreads();
    // after it=2 the cluster barrier below provides the block-wide sync
  }

  // ---------------- tail: per-row layer reconstruction + DSMEM add ----------
  CLUSTER_SYNC_();
  {
    const int r  = side * 32 + (tid >> 4), c4 = tid & 15;  // own half rows
    const int i4 = r * 16 + c4;
    // own-side selects
    const bool o1 = bitr(s.fr0[1], s.fr1[1], r);   // overwritten at it=1
    const bool o0 = (r == c_own);                  // overwritten at it=2
    // peer-side masks (computable locally: same adjacency, peer center = c_qry)
    const unsigned p10 = s.m0[c_qry] | (c_qry < 32 ? 1u << c_qry : 0u);
    const unsigned p11 = s.m1[c_qry] | (c_qry >= 32 ? 1u << (c_qry - 32) : 0u);
    const bool pp1 = bitr(p10, p11, r);
    const bool pp0 = (r == c_qry);

    const float4 oS = S4[i4];
    const float4 pS = ld_ds4(pbase + off_S + (uint32_t)i4 * 16u);
    const float4 o2 = o0 ? SV4[1024 + i4] : oS;
    const float4 p2 = pp0 ? ld_ds4(pbase + off_SAV + (uint32_t)(1024 + i4) * 16u) : pS;
    const float4 o1v = o1 ? SV4[i4] : o2;
    const float4 p1v = pp1 ? ld_ds4(pbase + off_SAV + (uint32_t)i4 * 16u) : p2;

    float* ob = out + (size_t)(base + r) * 256 + c4 * 4;
    *reinterpret_cast<float4*>(ob +  64) = sum4(o1v, p1v);
    *reinterpret_cast<float4*>(ob + 128) = sum4(o2,  p2);
    *reinterpret_cast<float4*>(ob + 192) = sum4(oS,  pS);
  }
  CLUSTER_SYNC_();   // peer may still be reading our smem
}

} // namespace

extern "C" void kernel_launch(void* const* d_in, const int* in_sizes, int n_in,
                              void* d_out, int out_size) {
  const float* adj       = (const float*)d_in[0];
  const float* feat_node = (const float*)d_in[1];
  const int*   idx       = (const int*)  d_in[2];
  const int*   head_ids  = (const int*)  d_in[3];
  const int*   tail_ids  = (const int*)  d_in[4];
  // d_in[5] = graph_indices (implicit in block layout)
  const float* transform = (const float*)d_in[6];
  const float* embed     = (const float*)d_in[7];
  const float* w1        = (const float*)d_in[8];
  const float* b1        = (const float*)d_in[9];
  const float* w2        = (const float*)d_in[10];
  const float* b2        = (const float*)d_in[11];
  const float* gamma1    = (const float*)d_in[12];
  const float* beta1     = (const float*)d_in[13];
  const float* gamma2    = (const float*)d_in[14];
  const float* beta2     = (const float*)d_in[15];
  float* out = (float*)d_out;

  const int smem = (int)sizeof(Smem);
  cudaFuncSetAttribute(lagat_kernel, cudaFuncAttributeMaxDynamicSharedMemorySize, smem);
  lagat_kernel<<<128, NT, smem>>>(adj, feat_node, idx, head_ids, tail_ids,
                                  transform, embed, w1, b1, w2, b2,
                                  gamma1, beta1, gamma2, beta2, out);
}

// round 13
// speedup vs baseline: 1.0260x; 1.0159x over previous
#include <cuda_runtime.h>
#include <cstdint>

namespace {

constexpr int NT = 512;  // threads per CTA (16 warps)

struct Smem {
  float F [64][64];
  float S [64][64];       // side state: H (side0) or T (side1)
  float U [64][64];       // xcat staging, then F + LN-out
  float W [64][64];       // w1 or w2
  float TR[64][64];       // transform (dead after P1)
  float WEb[2][64][64];   // ping-pong: cor[j] * S[j][:]
  float SAV[2][64][64];   // sparse row snapshots (pre-overwrite)
  unsigned m0[64], m1[64];    // adjacency bitmasks
  float degf[64];
  float gmm[64], bet[64], bias[64];
  unsigned fr0[4], fr1[4];    // frontier words per hop 0..3
  int   cnt[3];
  unsigned char tasks[3][64];
};

__device__ __forceinline__ float rsum16(float v, unsigned m) {
  v += __shfl_xor_sync(m, v, 8);
  v += __shfl_xor_sync(m, v, 4);
  v += __shfl_xor_sync(m, v, 2);
  v += __shfl_xor_sync(m, v, 1);
  return v;
}
__device__ __forceinline__ void fma4(float4& a, float s, const float4& b) {
  a.x = fmaf(s, b.x, a.x); a.y = fmaf(s, b.y, a.y);
  a.z = fmaf(s, b.z, a.z); a.w = fmaf(s, b.w, a.w);
}
__device__ __forceinline__ void add4(float4& a, const float4& b) {
  a.x += b.x; a.y += b.y; a.z += b.z; a.w += b.w;
}
__device__ __forceinline__ float4 sum4(const float4& a, const float4& b) {
  return make_float4(a.x + b.x, a.y + b.y, a.z + b.z, a.w + b.w);
}
__device__ __forceinline__ void relu4(float4& a) {
  a.x = fmaxf(a.x, 0.f); a.y = fmaxf(a.y, 0.f);
  a.z = fmaxf(a.z, 0.f); a.w = fmaxf(a.w, 0.f);
}
__device__ __forceinline__ bool bitr(unsigned w0, unsigned w1, int r) {
  return ((r < 32 ? (w0 >> r) : (w1 >> (r - 32))) & 1u) != 0u;
}
__device__ __forceinline__ uint32_t smem_u32(const void* p) {
  uint32_t a;
  asm("{ .reg .u64 t; cvta.to.shared.u64 t, %1; cvt.u32.u64 %0, t; }" : "=r"(a) : "l"(p));
  return a;
}
__device__ __forceinline__ uint32_t mapa_u32(uint32_t addr, uint32_t rank) {
  uint32_t r;
  asm("mapa.shared::cluster.u32 %0, %1, %2;" : "=r"(r) : "r"(addr), "r"(rank));
  return r;
}
__device__ __forceinline__ float4 ld_ds4(uint32_t addr) {
  uint32_t a, b, c, d;
  asm volatile("ld.shared::cluster.v4.b32 {%0,%1,%2,%3}, [%4];"
               : "=r"(a), "=r"(b), "=r"(c), "=r"(d) : "r"(addr));
  float4 v;
  v.x = __uint_as_float(a); v.y = __uint_as_float(b);
  v.z = __uint_as_float(c); v.w = __uint_as_float(d);
  return v;
}
#define CLUSTER_SYNC_() do { \
  asm volatile("barrier.cluster.arrive.aligned;" ::: "memory"); \
  asm volatile("barrier.cluster.wait.aligned;"   ::: "memory"); \
} while (0)

__global__ __launch_bounds__(NT, 1) __cluster_dims__(2, 1, 1)
void lagat_kernel(const float* __restrict__ adj,
                  const float* __restrict__ feat_node,
                  const int*   __restrict__ idx,
                  const int*   __restrict__ head_ids,
                  const int*   __restrict__ tail_ids,
                  const float* __restrict__ transform,
                  const float* __restrict__ embed,
                  const float* __restrict__ w1, const float* __restrict__ b1,
                  const float* __restrict__ w2, const float* __restrict__ b2,
                  const float* __restrict__ gamma1, const float* __restrict__ beta1,
                  const float* __restrict__ gamma2, const float* __restrict__ beta2,
                  float* __restrict__ out)
{
  extern __shared__ float smem_raw[];
  Smem& s = *reinterpret_cast<Smem*>(smem_raw);
  const int g    = blockIdx.x >> 1;
  const int side = blockIdx.x & 1;      // 0 = head chain, 1 = tail chain
  const int tid  = threadIdx.x;
  const int w    = tid >> 5;
  const int l    = tid & 31;
  const int li   = l & 15;
  const int h16  = l >> 4;
  const int hw   = w * 2 + h16;         // half-warp id 0..31
  const unsigned hm = (l < 16) ? 0x0000FFFFu : 0xFFFF0000u;
  const int base = g * 64;

  // ---- earliest: the only 2-deep dependent LDG chain (idx -> embed) --------
  const int xrow = tid >> 3, xcol = tid & 7;
  const int id = idx[base + xrow];                       // LDG #1 of chain
  const int hl = head_ids[g] - base;
  const int tl = tail_ids[g] - base;

  float4* F4  = reinterpret_cast<float4*>(&s.F [0][0]);
  float4* S4  = reinterpret_cast<float4*>(&s.S [0][0]);
  float4* U4  = reinterpret_cast<float4*>(&s.U [0][0]);
  float4* W4  = reinterpret_cast<float4*>(&s.W [0][0]);
  float4* TR4 = reinterpret_cast<float4*>(&s.TR[0][0]);
  float4* WEa = reinterpret_cast<float4*>(&s.WEb[0][0][0]);
  float4* WEbp= reinterpret_cast<float4*>(&s.WEb[1][0][0]);
  float4* SV4 = reinterpret_cast<float4*>(&s.SAV[0][0][0]);
  const float4* gm4 = reinterpret_cast<const float4*>(s.gmm);
  const float4* bt4 = reinterpret_cast<const float4*>(s.bet);
  const float4* bi4 = reinterpret_cast<const float4*>(s.bias);

  const uint32_t sbase   = smem_u32(&s);
  const uint32_t off_S   = (uint32_t)((const char*)&s.S[0][0]      - (const char*)&s);
  const uint32_t off_SAV = (uint32_t)((const char*)&s.SAV[0][0][0] - (const char*)&s);
  const uint32_t pbase   = mapa_u32(sbase, (uint32_t)(side ^ 1));

  const int c_own = side ? tl : hl;   // BFS center for this chain
  const int c_qry = side ? hl : tl;   // query center (opposite)

  const float* Wsrc = side ? w2 : w1;
  const float* Gsrc = side ? gamma2 : gamma1;
  const float* Bsrc = side ? beta2  : beta1;
  const float* bsrc = side ? b2 : b1;

  // ---------------- P0: loads + adjacency bitmask ---------------------------
  const float4 xg = *reinterpret_cast<const float4*>(embed + (size_t)id * 32 + xcol * 4);
  const float4 xf = *reinterpret_cast<const float4*>(feat_node + (base + xrow) * 32 + xcol * 4);
  {
    float av[4][2];
    #pragma unroll
    for (int rr = 0; rr < 4; ++rr) {
      const float* arow = adj + (size_t)(base + w * 4 + rr) * 4096 + base;
      av[rr][0] = arow[l];
      av[rr][1] = arow[l + 32];
    }
    #pragma unroll
    for (int rr = 0; rr < 4; ++rr) {
      const unsigned b0 = __ballot_sync(0xFFFFFFFFu, av[rr][0] != 0.f);
      const unsigned b1 = __ballot_sync(0xFFFFFFFFu, av[rr][1] != 0.f);
      if (l == 0) {
        const int r = w * 4 + rr;
        s.m0[r] = b0; s.m1[r] = b1;
        s.degf[r] = (float)(__popc(b0) + __popc(b1));
      }
    }
  }
  #pragma unroll
  for (int e = tid; e < 1024; e += NT) {
    TR4[e] = reinterpret_cast<const float4*>(transform)[e];
    W4[e]  = reinterpret_cast<const float4*>(Wsrc)[e];
  }
  U4[xrow * 16 + xcol]     = xf;
  U4[xrow * 16 + 8 + xcol] = xg;
  if (tid < 64) {
    s.gmm[tid] = Gsrc[tid]; s.bet[tid] = Bsrc[tid]; s.bias[tid] = bsrc[tid];
  }
  __syncthreads();

  // ---------------- P1: ALL 64 F rows, 2 rows per half-warp (W shared) ------
  {
    const int ra = hw;          // rows hw and hw+32
    const int rb = hw + 32;
    float4 aa = make_float4(0.f, 0.f, 0.f, 0.f);
    float4 ab = make_float4(0.f, 0.f, 0.f, 0.f);
    #pragma unroll
    for (int kb = 0; kb < 16; ++kb) {
      const float4 xa = U4[ra * 16 + kb];
      const float4 xb = U4[rb * 16 + kb];
      float4 wq;
      wq = TR4[(4 * kb + 0) * 16 + li]; fma4(aa, xa.x, wq); fma4(ab, xb.x, wq);
      wq = TR4[(4 * kb + 1) * 16 + li]; fma4(aa, xa.y, wq); fma4(ab, xb.y, wq);
      wq = TR4[(4 * kb + 2) * 16 + li]; fma4(aa, xa.z, wq); fma4(ab, xb.z, wq);
      wq = TR4[(4 * kb + 3) * 16 + li]; fma4(aa, xa.w, wq); fma4(ab, xb.w, wq);
    }
    F4[ra * 16 + li] = aa; S4[ra * 16 + li] = aa;
    F4[rb * 16 + li] = ab; S4[rb * 16 + li] = ab;
    if (side == 0) {
      *reinterpret_cast<float4*>(out + (size_t)(base + ra) * 256 + li * 4) = aa;
      *reinterpret_cast<float4*>(out + (size_t)(base + rb) * 256 + li * 4) = ab;
    }
  }

  // ---------------- frontier masks (hops 0..3) + task lists (warp 0) --------
  if (w == 0) {
    const unsigned c0bit = (c_own < 32) ? 1u << c_own : 0u;
    const unsigned c1bit = (c_own >= 32) ? 1u << (c_own - 32) : 0u;
    const unsigned f1_0 = s.m0[c_own] | c0bit;
    const unsigned f1_1 = s.m1[c_own] | c1bit;
    const bool a2 = bitr(f1_0, f1_1, l)      || (s.m0[l] & f1_0)      || (s.m1[l] & f1_1);
    const bool b2 = bitr(f1_0, f1_1, l + 32) || (s.m0[l + 32] & f1_0) || (s.m1[l + 32] & f1_1);
    const unsigned f2_0 = __ballot_sync(0xFFFFFFFFu, a2);
    const unsigned f2_1 = __ballot_sync(0xFFFFFFFFu, b2);
    const bool a3 = bitr(f2_0, f2_1, l)      || (s.m0[l] & f2_0)      || (s.m1[l] & f2_1);
    const bool b3 = bitr(f2_0, f2_1, l + 32) || (s.m0[l + 32] & f2_0) || (s.m1[l + 32] & f2_1);
    const unsigned f3_0 = __ballot_sync(0xFFFFFFFFu, a3);
    const unsigned f3_1 = __ballot_sync(0xFFFFFFFFu, b3);
    unsigned fw0[4] = { c0bit, f1_0, f2_0, f3_0 };
    unsigned fw1[4] = { c1bit, f1_1, f2_1, f3_1 };
    const unsigned below = (1u << l) - 1u;
    #pragma unroll
    for (int hp = 0; hp < 4; ++hp) {
      if (l == 0) { s.fr0[hp] = fw0[hp]; s.fr1[hp] = fw1[hp]; }
      if (hp < 3) {
        if ((fw0[hp] >> l) & 1u) s.tasks[hp][__popc(fw0[hp] & below)] = (unsigned char)l;
        if ((fw1[hp] >> l) & 1u) s.tasks[hp][__popc(fw0[hp]) + __popc(fw1[hp] & below)] = (unsigned char)(l + 32);
        if (l == 0) s.cnt[hp] = __popc(fw0[hp]) + __popc(fw1[hp]);
      }
    }
  }
  __syncthreads();

  // constants hoisted into registers for the whole main loop
  const float4 q   = F4[c_qry * 16 + li];
  const float4 ggr = gm4[li];
  const float4 bbr = bt4[li];
  const float4 bir = bi4[li];

  // ---------------- WE init (buffer 0) for fr[3] rows, from F ---------------
  {
    const unsigned nb0 = s.fr0[3], nb1 = s.fr1[3];
    #pragma unroll
    for (int p = 0; p < 2; ++p) {
      const int r = w * 4 + p * 2 + h16;
      if (bitr(nb0, nb1, r)) {
        const float4 sv = F4[r * 16 + li];
        float c = rsum16(sv.x * q.x + sv.y * q.y + sv.z * q.z + sv.w * q.w, hm);
        c = fabsf(c);
        WEa[r * 16 + li] = make_float4(c * sv.x, c * sv.y, c * sv.z, c * sv.w);
      }
    }
  }
  __syncthreads();

  // ---------------- main loop: it = 0,1,2 (hop = 2,1,0), fully unrolled -----
  #pragma unroll
  for (int it = 0; it < 3; ++it) {
    const int hop = 2 - it;
    const int cnt = s.cnt[hop];
    float4* WEc = (it & 1) ? WEbp : WEa;   // read buffer  (static after unroll)
    float4* WEn = (it & 1) ? WEa  : WEbp;  // write buffer (static after unroll)

    if (cnt > 32) {
      // ---- paired path: fused B+C, 2 tasks per half-warp, shared W reads ---
      for (int t2 = hw; 2 * t2 < cnt; t2 += 32) {
        const int ia = 2 * t2;
        const int ib = ia + 1;
        const int ra = s.tasks[hop][ia];
        const int rb = (ib < cnt) ? (int)s.tasks[hop][ib] : -1;

        #pragma unroll
        for (int qq = 0; qq < 2; ++qq) {
          const int r = qq ? rb : ra;
          if (r < 0) continue;
          unsigned mm0 = s.m0[r], mm1 = s.m1[r];
          float4 a0 = make_float4(0.f, 0.f, 0.f, 0.f);
          float4 a1 = make_float4(0.f, 0.f, 0.f, 0.f);
          while (mm0) { const int j = __ffs(mm0) - 1;  mm0 &= mm0 - 1; add4(a0, WEc[j * 16 + li]); }
          while (mm1) { const int j = __ffs(mm1) + 31; mm1 &= mm1 - 1; add4(a1, WEc[j * 16 + li]); }
          add4(a0, a1);
          a0.x = (a0.x >= 0.f) ? a0.x : 0.01f * a0.x;
          a0.y = (a0.y >= 0.f) ? a0.y : 0.01f * a0.y;
          a0.z = (a0.z >= 0.f) ? a0.z : 0.01f * a0.z;
          a0.w = (a0.w >= 0.f) ? a0.w : 0.01f * a0.w;
          const float inv = 1.f / (s.degf[r] + 1e-8f);
          a0.x *= inv; a0.y *= inv; a0.z *= inv; a0.w *= inv;
          // one-pass LN: two independent reduction chains (interleaved)
          float s1 = a0.x + a0.y + a0.z + a0.w;
          float s2 = a0.x * a0.x + a0.y * a0.y + a0.z * a0.z + a0.w * a0.w;
          s1 = rsum16(s1, hm);
          s2 = rsum16(s2, hm);
          const float mu  = s1 * (1.f / 64.f);
          const float var = fmaxf(s2 * (1.f / 64.f) - mu * mu, 0.f);
          const float rs  = rsqrtf(var + 1e-5f);
          const float4 d = make_float4(a0.x - mu, a0.y - mu, a0.z - mu, a0.w - mu);
          const float4 fv = F4[r * 16 + li];
          float4 u;
          u.x = fv.x + fmaf(ggr.x * rs, d.x, bbr.x);
          u.y = fv.y + fmaf(ggr.y * rs, d.y, bbr.y);
          u.z = fv.z + fmaf(ggr.z * rs, d.z, bbr.z);
          u.w = fv.w + fmaf(ggr.w * rs, d.w, bbr.w);
          U4[r * 16 + li] = u;
        }
        __syncwarp(hm);

        float4 aa = bir;
        float4 ab = bir;
        if (rb >= 0) {
          #pragma unroll
          for (int kb = 0; kb < 16; ++kb) {
            const float4 xa = U4[ra * 16 + kb];
            const float4 xb = U4[rb * 16 + kb];
            float4 wq;
            wq = W4[(4 * kb + 0) * 16 + li]; fma4(aa, xa.x, wq); fma4(ab, xb.x, wq);
            wq = W4[(4 * kb + 1) * 16 + li]; fma4(aa, xa.y, wq); fma4(ab, xb.y, wq);
            wq = W4[(4 * kb + 2) * 16 + li]; fma4(aa, xa.z, wq); fma4(ab, xb.z, wq);
            wq = W4[(4 * kb + 3) * 16 + li]; fma4(aa, xa.w, wq); fma4(ab, xb.w, wq);
          }
        } else {
          #pragma unroll
          for (int kb = 0; kb < 16; ++kb) {
            const float4 xv = U4[ra * 16 + kb];
            fma4(aa, xv.x, W4[(4 * kb + 0) * 16 + li]);
            fma4(aa, xv.y, W4[(4 * kb + 1) * 16 + li]);
            fma4(aa, xv.z, W4[(4 * kb + 2) * 16 + li]);
            fma4(aa, xv.w, W4[(4 * kb + 3) * 16 + li]);
          }
        }
        relu4(aa);
        if (it) SV4[(it - 1) * 1024 + ra * 16 + li] = S4[ra * 16 + li];
        S4[ra * 16 + li] = aa;
        if (it < 2) {
          float c = rsum16(aa.x * q.x + aa.y * q.y + aa.z * q.z + aa.w * q.w, hm);
          c = fabsf(c);
          WEn[ra * 16 + li] = make_float4(c * aa.x, c * aa.y, c * aa.z, c * aa.w);
        }
        if (rb >= 0) {
          relu4(ab);
          if (it) SV4[(it - 1) * 1024 + rb * 16 + li] = S4[rb * 16 + li];
          S4[rb * 16 + li] = ab;
          if (it < 2) {
            float c = rsum16(ab.x * q.x + ab.y * q.y + ab.z * q.z + ab.w * q.w, hm);
            c = fabsf(c);
            WEn[rb * 16 + li] = make_float4(c * ab.x, c * ab.y, c * ab.z, c * ab.w);
          }
        }
      }
    } else {
      // ---- serial path (R9 form): one task per half-warp, fused B+LN+GEMM --
      for (int t = hw; t < cnt; t += 32) {
        const int r = s.tasks[hop][t];
        unsigned mm0 = s.m0[r], mm1 = s.m1[r];
        float4 a0 = make_float4(0.f, 0.f, 0.f, 0.f);
        float4 a1 = make_float4(0.f, 0.f, 0.f, 0.f);
        while (mm0) { const int j = __ffs(mm0) - 1;  mm0 &= mm0 - 1; add4(a0, WEc[j * 16 + li]); }
        while (mm1) { const int j = __ffs(mm1) + 31; mm1 &= mm1 - 1; add4(a1, WEc[j * 16 + li]); }
        add4(a0, a1);
        a0.x = (a0.x >= 0.f) ? a0.x : 0.01f * a0.x;
        a0.y = (a0.y >= 0.f) ? a0.y : 0.01f * a0.y;
        a0.z = (a0.z >= 0.f) ? a0.z : 0.01f * a0.z;
        a0.w = (a0.w >= 0.f) ? a0.w : 0.01f * a0.w;
        const float inv = 1.f / (s.degf[r] + 1e-8f);
        a0.x *= inv; a0.y *= inv; a0.z *= inv; a0.w *= inv;
        float s1 = a0.x + a0.y + a0.z + a0.w;
        float s2 = a0.x * a0.x + a0.y * a0.y + a0.z * a0.z + a0.w * a0.w;
        s1 = rsum16(s1, hm);
        s2 = rsum16(s2, hm);
        const float mu  = s1 * (1.f / 64.f);
        const float var = fmaxf(s2 * (1.f / 64.f) - mu * mu, 0.f);
        const float rs  = rsqrtf(var + 1e-5f);
        const float4 d = make_float4(a0.x - mu, a0.y - mu, a0.z - mu, a0.w - mu);
        const float4 fv = F4[r * 16 + li];
        float4 u;
        u.x = fv.x + fmaf(ggr.x * rs, d.x, bbr.x);
        u.y = fv.y + fmaf(ggr.y * rs, d.y, bbr.y);
        u.z = fv.z + fmaf(ggr.z * rs, d.z, bbr.z);
        u.w = fv.w + fmaf(ggr.w * rs, d.w, bbr.w);
        U4[r * 16 + li] = u;
        __syncwarp(hm);

        float4 acc = bir;
        #pragma unroll
        for (int kb = 0; kb < 16; ++kb) {
          const float4 xv = U4[r * 16 + kb];
          fma4(acc, xv.x, W4[(4 * kb + 0) * 16 + li]);
          fma4(acc, xv.y, W4[(4 * kb + 1) * 16 + li]);
          fma4(acc, xv.z, W4[(4 * kb + 2) * 16 + li]);
          fma4(acc, xv.w, W4[(4 * kb + 3) * 16 + li]);
        }
        relu4(acc);
        if (it) SV4[(it - 1) * 1024 + r * 16 + li] = S4[r * 16 + li];
        S4[r * 16 + li] = acc;
        if (it < 2) {
          float c = rsum16(acc.x * q.x + acc.y * q.y + acc.z * q.z + acc.w * q.w, hm);
          c = fabsf(c);
          WEn[r * 16 + li] = make_float4(c * acc.x, c * acc.y, c * acc.z, c * acc.w);
        }
      }
    }
    if (it < 2) __syncthreads();
    // after it=2 the cluster barrier below provides the block-wide sync
  }

  // ---------------- tail: per-row layer reconstruction + DSMEM add ----------
  CLUSTER_SYNC_();
  {
    const int r  = side * 32 + (tid >> 4), c4 = tid & 15;  // own half rows
    const int i4 = r * 16 + c4;
    // own-side selects
    const bool o1 = bitr(s.fr0[1], s.fr1[1], r);   // overwritten at it=1
    const bool o0 = (r == c_own);                  // overwritten at it=2
    // peer-side masks (computable locally: same adjacency, peer center = c_qry)
    const unsigned p10 = s.m0[c_qry] | (c_qry < 32 ? 1u << c_qry : 0u);
    const unsigned p11 = s.m1[c_qry] | (c_qry >= 32 ? 1u << (c_qry - 32) : 0u);
    const bool pp1 = bitr(p10, p11, r);
    const bool pp0 = (r == c_qry);

    const float4 oS = S4[i4];
    const float4 pS = ld_ds4(pbase + off_S + (uint32_t)i4 * 16u);
    const float4 o2 = o0 ? SV4[1024 + i4] : oS;
    const float4 p2 = pp0 ? ld_ds4(pbase + off_SAV + (uint32_t)(1024 + i4) * 16u) : pS;
    const float4 o1v = o1 ? SV4[i4] : o2;
    const float4 p1v = pp1 ? ld_ds4(pbase + off_SAV + (uint32_t)i4 * 16u) : p2;

    float* ob = out + (size_t)(base + r) * 256 + c4 * 4;
    *reinterpret_cast<float4*>(ob +  64) = sum4(o1v, p1v);
    *reinterpret_cast<float4*>(ob + 128) = sum4(o2,  p2);
    *reinterpret_cast<float4*>(ob + 192) = sum4(oS,  pS);
  }
  CLUSTER_SYNC_();   // peer may still be reading our smem
}

} // namespace

extern "C" void kernel_launch(void* const* d_in, const int* in_sizes, int n_in,
                              void* d_out, int out_size) {
  const float* adj       = (const float*)d_in[0];
  const float* feat_node = (const float*)d_in[1];
  const int*   idx       = (const int*)  d_in[2];
  const int*   head_ids  = (const int*)  d_in[3];
  const int*   tail_ids  = (const int*)  d_in[4];
  // d_in[5] = graph_indices (implicit in block layout)
  const float* transform = (const float*)d_in[6];
  const float* embed     = (const float*)d_in[7];
  const float* w1        = (const float*)d_in[8];
  const float* b1        = (const float*)d_in[9];
  const float* w2        = (const float*)d_in[10];
  const float* b2        = (const float*)d_in[11];
  const float* gamma1    = (const float*)d_in[12];
  const float* beta1     = (const float*)d_in[13];
  const float* gamma2    = (const float*)d_in[14];
  const float* beta2     = (const float*)d_in[15];
  float* out = (float*)d_out;

  const int smem = (int)sizeof(Smem);
  cudaFuncSetAttribute(lagat_kernel, cudaFuncAttributeMaxDynamicSharedMemorySize, smem);
  lagat_kernel<<<128, NT, smem>>>(adj, feat_node, idx, head_ids, tail_ids,
                                  transform, embed, w1, b1, w2, b2,
                                  gamma1, beta1, gamma2, beta2, out);
}

// round 14
// speedup vs baseline: 1.0660x; 1.0390x over previous
#include <cuda_runtime.h>
#include <cstdint>

namespace {

constexpr int NT = 512;  // threads per CTA (16 warps)

struct Smem {
  float F [64][64];
  float S [64][64];       // side state: H (side0) or T (side1)
  float U [64][64];       // xcat staging, then F + LN-out
  float W [64][64];       // w1 or w2
  float TR[64][64];       // transform (dead after P1)
  float WEb[2][64][64];   // ping-pong: cor[j] * S[j][:]
  float SAV[2][64][64];   // sparse row snapshots (pre-overwrite)
  unsigned m0[64], m1[64];    // adjacency bitmasks
  float invdeg[64];           // 1 / (deg + 1e-8), precomputed
  float gmm[64], bet[64], bias[64];
  unsigned fr0[4], fr1[4];    // frontier words per hop 0..3
  int   cnt[3];
  unsigned char tasks[3][64];
};

__device__ __forceinline__ float rsum16(float v, unsigned m) {
  v += __shfl_xor_sync(m, v, 8);
  v += __shfl_xor_sync(m, v, 4);
  v += __shfl_xor_sync(m, v, 2);
  v += __shfl_xor_sync(m, v, 1);
  return v;
}
__device__ __forceinline__ void fma4(float4& a, float s, const float4& b) {
  a.x = fmaf(s, b.x, a.x); a.y = fmaf(s, b.y, a.y);
  a.z = fmaf(s, b.z, a.z); a.w = fmaf(s, b.w, a.w);
}
__device__ __forceinline__ void add4(float4& a, const float4& b) {
  a.x += b.x; a.y += b.y; a.z += b.z; a.w += b.w;
}
__device__ __forceinline__ float4 sum4(const float4& a, const float4& b) {
  return make_float4(a.x + b.x, a.y + b.y, a.z + b.z, a.w + b.w);
}
__device__ __forceinline__ void relu4(float4& a) {
  a.x = fmaxf(a.x, 0.f); a.y = fmaxf(a.y, 0.f);
  a.z = fmaxf(a.z, 0.f); a.w = fmaxf(a.w, 0.f);
}
__device__ __forceinline__ bool bitr(unsigned w0, unsigned w1, int r) {
  return ((r < 32 ? (w0 >> r) : (w1 >> (r - 32))) & 1u) != 0u;
}
__device__ __forceinline__ uint32_t smem_u32(const void* p) {
  uint32_t a;
  asm("{ .reg .u64 t; cvta.to.shared.u64 t, %1; cvt.u32.u64 %0, t; }" : "=r"(a) : "l"(p));
  return a;
}
__device__ __forceinline__ uint32_t mapa_u32(uint32_t addr, uint32_t rank) {
  uint32_t r;
  asm("mapa.shared::cluster.u32 %0, %1, %2;" : "=r"(r) : "r"(addr), "r"(rank));
  return r;
}
__device__ __forceinline__ float4 ld_ds4(uint32_t addr) {
  uint32_t a, b, c, d;
  asm volatile("ld.shared::cluster.v4.b32 {%0,%1,%2,%3}, [%4];"
               : "=r"(a), "=r"(b), "=r"(c), "=r"(d) : "r"(addr));
  float4 v;
  v.x = __uint_as_float(a); v.y = __uint_as_float(b);
  v.z = __uint_as_float(c); v.w = __uint_as_float(d);
  return v;
}
#define CLUSTER_SYNC_() do { \
  asm volatile("barrier.cluster.arrive.aligned;" ::: "memory"); \
  asm volatile("barrier.cluster.wait.aligned;"   ::: "memory"); \
} while (0)

__global__ __launch_bounds__(NT, 1) __cluster_dims__(2, 1, 1)
void lagat_kernel(const float* __restrict__ adj,
                  const float* __restrict__ feat_node,
                  const int*   __restrict__ idx,
                  const int*   __restrict__ head_ids,
                  const int*   __restrict__ tail_ids,
                  const float* __restrict__ transform,
                  const float* __restrict__ embed,
                  const float* __restrict__ w1, const float* __restrict__ b1,
                  const float* __restrict__ w2, const float* __restrict__ b2,
                  const float* __restrict__ gamma1, const float* __restrict__ beta1,
                  const float* __restrict__ gamma2, const float* __restrict__ beta2,
                  float* __restrict__ out)
{
  extern __shared__ float smem_raw[];
  Smem& s = *reinterpret_cast<Smem*>(smem_raw);
  const int g    = blockIdx.x >> 1;
  const int side = blockIdx.x & 1;      // 0 = head chain, 1 = tail chain
  const int tid  = threadIdx.x;
  const int w    = tid >> 5;
  const int l    = tid & 31;
  const int li   = l & 15;
  const int h16  = l >> 4;
  const int hw   = w * 2 + h16;         // half-warp id 0..31
  const unsigned hm = (l < 16) ? 0x0000FFFFu : 0xFFFF0000u;
  const int base = g * 64;

  // ---- earliest: the only 2-deep dependent LDG chain (idx -> embed) --------
  const int xrow = tid >> 3, xcol = tid & 7;
  const int id = idx[base + xrow];                       // LDG #1 of chain
  const int hl = head_ids[g] - base;
  const int tl = tail_ids[g] - base;

  float4* F4  = reinterpret_cast<float4*>(&s.F [0][0]);
  float4* S4  = reinterpret_cast<float4*>(&s.S [0][0]);
  float4* U4  = reinterpret_cast<float4*>(&s.U [0][0]);
  float4* W4  = reinterpret_cast<float4*>(&s.W [0][0]);
  float4* TR4 = reinterpret_cast<float4*>(&s.TR[0][0]);
  float4* WEa = reinterpret_cast<float4*>(&s.WEb[0][0][0]);
  float4* WEbp= reinterpret_cast<float4*>(&s.WEb[1][0][0]);
  float4* SV4 = reinterpret_cast<float4*>(&s.SAV[0][0][0]);
  const float4* gm4 = reinterpret_cast<const float4*>(s.gmm);
  const float4* bt4 = reinterpret_cast<const float4*>(s.bet);
  const float4* bi4 = reinterpret_cast<const float4*>(s.bias);

  const uint32_t sbase   = smem_u32(&s);
  const uint32_t off_S   = (uint32_t)((const char*)&s.S[0][0]      - (const char*)&s);
  const uint32_t off_SAV = (uint32_t)((const char*)&s.SAV[0][0][0] - (const char*)&s);
  const uint32_t pbase   = mapa_u32(sbase, (uint32_t)(side ^ 1));

  const int c_own = side ? tl : hl;   // BFS center for this chain
  const int c_qry = side ? hl : tl;   // query center (opposite)

  const float* Wsrc = side ? w2 : w1;
  const float* Gsrc = side ? gamma2 : gamma1;
  const float* Bsrc = side ? beta2  : beta1;
  const float* bsrc = side ? b2 : b1;

  // ---------------- P0: loads + adjacency bitmask ---------------------------
  const float4 xg = *reinterpret_cast<const float4*>(embed + (size_t)id * 32 + xcol * 4);
  const float4 xf = *reinterpret_cast<const float4*>(feat_node + (base + xrow) * 32 + xcol * 4);
  {
    float av[4][2];
    #pragma unroll
    for (int rr = 0; rr < 4; ++rr) {
      const float* arow = adj + (size_t)(base + w * 4 + rr) * 4096 + base;
      av[rr][0] = arow[l];
      av[rr][1] = arow[l + 32];
    }
    #pragma unroll
    for (int rr = 0; rr < 4; ++rr) {
      const unsigned b0 = __ballot_sync(0xFFFFFFFFu, av[rr][0] != 0.f);
      const unsigned b1 = __ballot_sync(0xFFFFFFFFu, av[rr][1] != 0.f);
      if (l == 0) {
        const int r = w * 4 + rr;
        s.m0[r] = b0; s.m1[r] = b1;
        s.invdeg[r] = 1.f / ((float)(__popc(b0) + __popc(b1)) + 1e-8f);
      }
    }
  }
  #pragma unroll
  for (int e = tid; e < 1024; e += NT) {
    TR4[e] = reinterpret_cast<const float4*>(transform)[e];
    W4[e]  = reinterpret_cast<const float4*>(Wsrc)[e];
  }
  U4[xrow * 16 + xcol]     = xf;
  U4[xrow * 16 + 8 + xcol] = xg;
  if (tid < 64) {
    s.gmm[tid] = Gsrc[tid]; s.bet[tid] = Bsrc[tid]; s.bias[tid] = bsrc[tid];
  }
  __syncthreads();

  // ---------------- P1: ALL 64 F rows, 2 rows per half-warp (W shared) ------
  // layer-0 STG split: side0 stores rows 0-31 (ra), side1 stores rows 32-63 (rb)
  {
    const int ra = hw;          // rows hw and hw+32
    const int rb = hw + 32;
    float4 aa = make_float4(0.f, 0.f, 0.f, 0.f);
    float4 ab = make_float4(0.f, 0.f, 0.f, 0.f);
    #pragma unroll
    for (int kb = 0; kb < 16; ++kb) {
      const float4 xa = U4[ra * 16 + kb];
      const float4 xb = U4[rb * 16 + kb];
      float4 wq;
      wq = TR4[(4 * kb + 0) * 16 + li]; fma4(aa, xa.x, wq); fma4(ab, xb.x, wq);
      wq = TR4[(4 * kb + 1) * 16 + li]; fma4(aa, xa.y, wq); fma4(ab, xb.y, wq);
      wq = TR4[(4 * kb + 2) * 16 + li]; fma4(aa, xa.z, wq); fma4(ab, xb.z, wq);
      wq = TR4[(4 * kb + 3) * 16 + li]; fma4(aa, xa.w, wq); fma4(ab, xb.w, wq);
    }
    F4[ra * 16 + li] = aa; S4[ra * 16 + li] = aa;
    F4[rb * 16 + li] = ab; S4[rb * 16 + li] = ab;
    if (side == 0) {
      *reinterpret_cast<float4*>(out + (size_t)(base + ra) * 256 + li * 4) = aa;
    } else {
      *reinterpret_cast<float4*>(out + (size_t)(base + rb) * 256 + li * 4) = ab;
    }
  }

  // ---------------- frontier masks (hops 0..3) + task lists (warp 0) --------
  if (w == 0) {
    const unsigned c0bit = (c_own < 32) ? 1u << c_own : 0u;
    const unsigned c1bit = (c_own >= 32) ? 1u << (c_own - 32) : 0u;
    const unsigned f1_0 = s.m0[c_own] | c0bit;
    const unsigned f1_1 = s.m1[c_own] | c1bit;
    const bool a2 = bitr(f1_0, f1_1, l)      || (s.m0[l] & f1_0)      || (s.m1[l] & f1_1);
    const bool b2 = bitr(f1_0, f1_1, l + 32) || (s.m0[l + 32] & f1_0) || (s.m1[l + 32] & f1_1);
    const unsigned f2_0 = __ballot_sync(0xFFFFFFFFu, a2);
    const unsigned f2_1 = __ballot_sync(0xFFFFFFFFu, b2);
    const bool a3 = bitr(f2_0, f2_1, l)      || (s.m0[l] & f2_0)      || (s.m1[l] & f2_1);
    const bool b3 = bitr(f2_0, f2_1, l + 32) || (s.m0[l + 32] & f2_0) || (s.m1[l + 32] & f2_1);
    const unsigned f3_0 = __ballot_sync(0xFFFFFFFFu, a3);
    const unsigned f3_1 = __ballot_sync(0xFFFFFFFFu, b3);
    unsigned fw0[4] = { c0bit, f1_0, f2_0, f3_0 };
    unsigned fw1[4] = { c1bit, f1_1, f2_1, f3_1 };
    const unsigned below = (1u << l) - 1u;
    #pragma unroll
    for (int hp = 0; hp < 4; ++hp) {
      if (l == 0) { s.fr0[hp] = fw0[hp]; s.fr1[hp] = fw1[hp]; }
      if (hp < 3) {
        if ((fw0[hp] >> l) & 1u) s.tasks[hp][__popc(fw0[hp] & below)] = (unsigned char)l;
        if ((fw1[hp] >> l) & 1u) s.tasks[hp][__popc(fw0[hp]) + __popc(fw1[hp] & below)] = (unsigned char)(l + 32);
        if (l == 0) s.cnt[hp] = __popc(fw0[hp]) + __popc(fw1[hp]);
      }
    }
  }
  __syncthreads();

  // constants hoisted into registers for the whole main loop
  const float4 q   = F4[c_qry * 16 + li];
  const float4 ggr = gm4[li];
  const float4 bbr = bt4[li];
  const float4 bir = bi4[li];

  // ---------------- WE init (buffer 0) for fr[3] rows, from F ---------------
  {
    const unsigned nb0 = s.fr0[3], nb1 = s.fr1[3];
    #pragma unroll
    for (int p = 0; p < 2; ++p) {
      const int r = w * 4 + p * 2 + h16;
      if (bitr(nb0, nb1, r)) {
        const float4 sv = F4[r * 16 + li];
        float c = rsum16(sv.x * q.x + sv.y * q.y + sv.z * q.z + sv.w * q.w, hm);
        c = fabsf(c);
        WEa[r * 16 + li] = make_float4(c * sv.x, c * sv.y, c * sv.z, c * sv.w);
      }
    }
  }
  __syncthreads();

  // ---------------- main loop: it = 0,1,2 (hop = 2,1,0), fully unrolled -----
  #pragma unroll
  for (int it = 0; it < 3; ++it) {
    const int hop = 2 - it;
    const int cnt = s.cnt[hop];
    float4* WEc = (it & 1) ? WEbp : WEa;   // read buffer  (static after unroll)
    float4* WEn = (it & 1) ? WEa  : WEbp;  // write buffer (static after unroll)

    if (cnt > 32) {
      // ---- paired path: fused B+C, 2 tasks per half-warp, shared W reads ---
      for (int t2 = hw; 2 * t2 < cnt; t2 += 32) {
        const int ia = 2 * t2;
        const int ib = ia + 1;
        const int ra = s.tasks[hop][ia];
        const int rb = (ib < cnt) ? (int)s.tasks[hop][ib] : -1;

        #pragma unroll
        for (int qq = 0; qq < 2; ++qq) {
          const int r = qq ? rb : ra;
          if (r < 0) continue;
          unsigned mm0 = s.m0[r], mm1 = s.m1[r];
          float4 a0 = make_float4(0.f, 0.f, 0.f, 0.f);
          float4 a1 = make_float4(0.f, 0.f, 0.f, 0.f);
          while (mm0) { const int j = __ffs(mm0) - 1;  mm0 &= mm0 - 1; add4(a0, WEc[j * 16 + li]); }
          while (mm1) { const int j = __ffs(mm1) + 31; mm1 &= mm1 - 1; add4(a1, WEc[j * 16 + li]); }
          add4(a0, a1);
          a0.x = (a0.x >= 0.f) ? a0.x : 0.01f * a0.x;
          a0.y = (a0.y >= 0.f) ? a0.y : 0.01f * a0.y;
          a0.z = (a0.z >= 0.f) ? a0.z : 0.01f * a0.z;
          a0.w = (a0.w >= 0.f) ? a0.w : 0.01f * a0.w;
          const float inv = s.invdeg[r];
          a0.x *= inv; a0.y *= inv; a0.z *= inv; a0.w *= inv;
          // one-pass LN: two independent reduction chains (interleaved)
          float s1 = a0.x + a0.y + a0.z + a0.w;
          float s2 = a0.x * a0.x + a0.y * a0.y + a0.z * a0.z + a0.w * a0.w;
          s1 = rsum16(s1, hm);
          s2 = rsum16(s2, hm);
          const float mu  = s1 * (1.f / 64.f);
          const float var = fmaxf(s2 * (1.f / 64.f) - mu * mu, 0.f);
          const float rs  = rsqrtf(var + 1e-5f);
          const float4 d = make_float4(a0.x - mu, a0.y - mu, a0.z - mu, a0.w - mu);
          const float4 fv = F4[r * 16 + li];
          float4 u;
          u.x = fv.x + fmaf(ggr.x * rs, d.x, bbr.x);
          u.y = fv.y + fmaf(ggr.y * rs, d.y, bbr.y);
          u.z = fv.z + fmaf(ggr.z * rs, d.z, bbr.z);
          u.w = fv.w + fmaf(ggr.w * rs, d.w, bbr.w);
          U4[r * 16 + li] = u;
        }
        __syncwarp(hm);

        float4 aa = bir;
        float4 ab = bir;
        if (rb >= 0) {
          #pragma unroll
          for (int kb = 0; kb < 16; ++kb) {
            const float4 xa = U4[ra * 16 + kb];
            const float4 xb = U4[rb * 16 + kb];
            float4 wq;
            wq = W4[(4 * kb + 0) * 16 + li]; fma4(aa, xa.x, wq); fma4(ab, xb.x, wq);
            wq = W4[(4 * kb + 1) * 16 + li]; fma4(aa, xa.y, wq); fma4(ab, xb.y, wq);
            wq = W4[(4 * kb + 2) * 16 + li]; fma4(aa, xa.z, wq); fma4(ab, xb.z, wq);
            wq = W4[(4 * kb + 3) * 16 + li]; fma4(aa, xa.w, wq); fma4(ab, xb.w, wq);
          }
        } else {
          #pragma unroll
          for (int kb = 0; kb < 16; ++kb) {
            const float4 xv = U4[ra * 16 + kb];
            fma4(aa, xv.x, W4[(4 * kb + 0) * 16 + li]);
            fma4(aa, xv.y, W4[(4 * kb + 1) * 16 + li]);
            fma4(aa, xv.z, W4[(4 * kb + 2) * 16 + li]);
            fma4(aa, xv.w, W4[(4 * kb + 3) * 16 + li]);
          }
        }
        relu4(aa);
        if (it) SV4[(it - 1) * 1024 + ra * 16 + li] = S4[ra * 16 + li];
        S4[ra * 16 + li] = aa;
        if (it < 2) {
          float c = rsum16(aa.x * q.x + aa.y * q.y + aa.z * q.z + aa.w * q.w, hm);
          c = fabsf(c);
          WEn[ra * 16 + li] = make_float4(c * aa.x, c * aa.y, c * aa.z, c * aa.w);
        }
        if (rb >= 0) {
          relu4(ab);
          if (it) SV4[(it - 1) * 1024 + rb * 16 + li] = S4[rb * 16 + li];
          S4[rb * 16 + li] = ab;
          if (it < 2) {
            float c = rsum16(ab.x * q.x + ab.y * q.y + ab.z * q.z + ab.w * q.w, hm);
            c = fabsf(c);
            WEn[rb * 16 + li] = make_float4(c * ab.x, c * ab.y, c * ab.z, c * ab.w);
          }
        }
      }
    } else {
      // ---- serial path (R9 form): one task per half-warp, fused B+LN+GEMM --
      for (int t = hw; t < cnt; t += 32) {
        const int r = s.tasks[hop][t];
        unsigned mm0 = s.m0[r], mm1 = s.m1[r];
        float4 a0 = make_float4(0.f, 0.f, 0.f, 0.f);
        float4 a1 = make_float4(0.f, 0.f, 0.f, 0.f);
        while (mm0) { const int j = __ffs(mm0) - 1;  mm0 &= mm0 - 1; add4(a0, WEc[j * 16 + li]); }
        while (mm1) { const int j = __ffs(mm1) + 31; mm1 &= mm1 - 1; add4(a1, WEc[j * 16 + li]); }
        add4(a0, a1);
        a0.x = (a0.x >= 0.f) ? a0.x : 0.01f * a0.x;
        a0.y = (a0.y >= 0.f) ? a0.y : 0.01f * a0.y;
        a0.z = (a0.z >= 0.f) ? a0.z : 0.01f * a0.z;
        a0.w = (a0.w >= 0.f) ? a0.w : 0.01f * a0.w;
        const float inv = s.invdeg[r];
        a0.x *= inv; a0.y *= inv; a0.z *= inv; a0.w *= inv;
        float s1 = a0.x + a0.y + a0.z + a0.w;
        float s2 = a0.x * a0.x + a0.y * a0.y + a0.z * a0.z + a0.w * a0.w;
        s1 = rsum16(s1, hm);
        s2 = rsum16(s2, hm);
        const float mu  = s1 * (1.f / 64.f);
        const float var = fmaxf(s2 * (1.f / 64.f) - mu * mu, 0.f);
        const float rs  = rsqrtf(var + 1e-5f);
        const float4 d = make_float4(a0.x - mu, a0.y - mu, a0.z - mu, a0.w - mu);
        const float4 fv = F4[r * 16 + li];
        float4 u;
        u.x = fv.x + fmaf(ggr.x * rs, d.x, bbr.x);
        u.y = fv.y + fmaf(ggr.y * rs, d.y, bbr.y);
        u.z = fv.z + fmaf(ggr.z * rs, d.z, bbr.z);
        u.w = fv.w + fmaf(ggr.w * rs, d.w, bbr.w);
        U4[r * 16 + li] = u;
        __syncwarp(hm);

        float4 acc = bir;
        #pragma unroll
        for (int kb = 0; kb < 16; ++kb) {
          const float4 xv = U4[r * 16 + kb];
          fma4(acc, xv.x, W4[(4 * kb + 0) * 16 + li]);
          fma4(acc, xv.y, W4[(4 * kb + 1) * 16 + li]);
          fma4(acc, xv.z, W4[(4 * kb + 2) * 16 + li]);
          fma4(acc, xv.w, W4[(4 * kb + 3) * 16 + li]);
        }
        relu4(acc);
        if (it) SV4[(it - 1) * 1024 + r * 16 + li] = S4[r * 16 + li];
        S4[r * 16 + li] = acc;
        if (it < 2) {
          float c = rsum16(acc.x * q.x + acc.y * q.y + acc.z * q.z + acc.w * q.w, hm);
          c = fabsf(c);
          WEn[r * 16 + li] = make_float4(c * acc.x, c * acc.y, c * acc.z, c * acc.w);
        }
      }
    }
    if (it < 2) __syncthreads();
    // after it=2 the cluster barrier below provides the block-wide sync
  }

  // ---------------- tail: per-row layer reconstruction + DSMEM add ----------
  CLUSTER_SYNC_();
  {
    const int r  = side * 32 + (tid >> 4), c4 = tid & 15;  // own half rows
    const int i4 = r * 16 + c4;
    // own-side selects
    const bool o1 = bitr(s.fr0[1], s.fr1[1], r);   // overwritten at it=1
    const bool o0 = (r == c_own);                  // overwritten at it=2
    // peer-side masks (computable locally: same adjacency, peer center = c_qry)
    const unsigned p10 = s.m0[c_qry] | (c_qry < 32 ? 1u << c_qry : 0u);
    const unsigned p11 = s.m1[c_qry] | (c_qry >= 32 ? 1u << (c_qry - 32) : 0u);
    const bool pp1 = bitr(p10, p11, r);
    const bool pp0 = (r == c_qry);

    const float4 oS = S4[i4];
    const float4 pS = ld_ds4(pbase + off_S + (uint32_t)i4 * 16u);
    const float4 o2 = o0 ? SV4[1024 + i4] : oS;
    const float4 p2 = pp0 ? ld_ds4(pbase + off_SAV + (uint32_t)(1024 + i4) * 16u) : pS;
    const float4 o1v = o1 ? SV4[i4] : o2;
    const float4 p1v = pp1 ? ld_ds4(pbase + off_SAV + (uint32_t)i4 * 16u) : p2;

    float* ob = out + (size_t)(base + r) * 256 + c4 * 4;
    *reinterpret_cast<float4*>(ob +  64) = sum4(o1v, p1v);
    *reinterpret_cast<float4*>(ob + 128) = sum4(o2,  p2);
    *reinterpret_cast<float4*>(ob + 192) = sum4(oS,  pS);
  }
  CLUSTER_SYNC_();   // peer may still be reading our smem
}

} // namespace

extern "C" void kernel_launch(void* const* d_in, const int* in_sizes, int n_in,
                              void* d_out, int out_size) {
  const float* adj       = (const float*)d_in[0];
  const float* feat_node = (const float*)d_in[1];
  const int*   idx       = (const int*)  d_in[2];
  const int*   head_ids  = (const int*)  d_in[3];
  const int*   tail_ids  = (const int*)  d_in[4];
  // d_in[5] = graph_indices (implicit in block layout)
  const float* transform = (const float*)d_in[6];
  const float* embed     = (const float*)d_in[7];
  const float* w1        = (const float*)d_in[8];
  const float* b1        = (const float*)d_in[9];
  const float* w2        = (const float*)d_in[10];
  const float* b2        = (const float*)d_in[11];
  const float* gamma1    = (const float*)d_in[12];
  const float* beta1     = (const float*)d_in[13];
  const float* gamma2    = (const float*)d_in[14];
  const float* beta2     = (const float*)d_in[15];
  float* out = (float*)d_out;

  const int smem = (int)sizeof(Smem);
  cudaFuncSetAttribute(lagat_kernel, cudaFuncAttributeMaxDynamicSharedMemorySize, smem);
  lagat_kernel<<<128, NT, smem>>>(adj, feat_node, idx, head_ids, tail_ids,
                                  transform, embed, w1, b1, w2, b2,
                                  gamma1, beta1, gamma2, beta2, out);
}